// round 7
// baseline (speedup 1.0000x reference)
#include <cuda_runtime.h>

// ---------------------------------------------------------------------------
// Two kernels:
//  precomp_kernel (3000 thr): per-line constants -> __device__ globals (once,
//      instead of redundantly in all 148 CTAs).
//  fused_kernel: CTA = 676-px chunk (grid 148 = one wave, BLOCK 704).
//    far  (> 20 A): linearized lorentz at 4 chunk nodes, accumulated inline
//         while streaming g_A once (batched 4-node rcp).
//    mid  (4..20 A): linearized lorentz at 16 uniform nodes, piecewise cubic.
//    near (<= 4 A): exact product; paired rcp outside the +-3 A gaussian-alive
//         window (found by per-warp binary search), full voigt inside.
//  Boundary indices via running max + atomicMax during the streaming pass.
// Error budget: linearization ~1e-6, mid interp ~1e-5, gauss cutoff ~1e-6.
// ---------------------------------------------------------------------------

#define BLOCK     704
#define NWARPS    22
#define CHUNK     676
#define NWIN      4.0f
#define AWIN      20.0f
#define GWIN      3.0f
#define SMEM_CAP  192
#define MAX_LINES 4096
#define LOG2E     1.4426950408889634f

__device__ float4 g_A[MAX_LINES];   // {lam, g^2, c_lor, m}
__device__ float  g_B[MAX_LINES];   // c_gauss

__device__ __forceinline__ float frcp(float x) {
    float r; asm("rcp.approx.ftz.f32 %0, %1;" : "=f"(r) : "f"(x)); return r;
}
__device__ __forceinline__ float fex2(float x) {
    float r; asm("ex2.approx.ftz.f32 %0, %1;" : "=f"(r) : "f"(x)); return r;
}
__device__ __forceinline__ float flg2(float x) {
    float r; asm("lg2.approx.ftz.f32 %0, %1;" : "=f"(r) : "f"(x)); return r;
}

__global__ void precomp_kernel(const float* __restrict__ lam,
                               const float* __restrict__ amps,
                               const float* __restrict__ sw,
                               const float* __restrict__ gw,
                               int L) {
    int l = blockIdx.x * blockDim.x + threadIdx.x;
    if (l >= L) return;

    float sigma = fex2(sw[l] * LOG2E);
    float gamma = fex2(gw[l] * LOG2E);
    float amp   = fex2(amps[l] * LOG2E);
    float fg = 2.3548f * sigma;
    float fl = 2.0f * gamma;
    float fg2 = fg * fg;
    float fl2 = fl * fl;
    float poly = fg2 * fg2 * fg
               + 2.69269f * fg2 * fg2 * fl
               + 2.42843f * fg2 * fg  * fl2
               + 4.47163f * fg2 * fl  * fl2
               + 0.07842f * fg  * fl2 * fl2
               + fl2 * fl2 * fl;
    float fr  = fl * fex2(-0.2f * flg2(poly));     // fl * poly^(-1/5)
    float eta = fr * (1.36603f + fr * (-0.47719f + fr * 0.11116f));
    float invs = frcp(sigma);

    g_A[l] = make_float4(lam[l],
                         gamma * gamma,
                         amp * eta * gamma * 0.3183098862f,     // /pi
                         -0.72134752f * invs * invs);           // -0.5*log2e/s^2
    g_B[l] = amp * (1.0f - eta) * invs * 0.39894228f;           // /2.5066
}

__global__ void __launch_bounds__(BLOCK)
fused_kernel(const float* __restrict__ wl, int npix, int L,
             const float* __restrict__ pa,
             const float* __restrict__ pb,
             const float* __restrict__ pc,
             float* __restrict__ out) {
    __shared__ float4 sA[SMEM_CAP];
    __shared__ float  sB[SMEM_CAP];
    __shared__ float  sWredF[4 * NWARPS];
    __shared__ float  sS[4];
    __shared__ float  sMid[16];
    __shared__ int    sIdx[4];

    const int tid  = threadIdx.x;
    const int w    = tid >> 5, lane = tid & 31;
    const int p0   = blockIdx.x * CHUNK;
    const int cnt  = min(CHUNK, npix - p0);

    const float wlLo = wl[p0];
    const float wlHi = wl[p0 + cnt - 1];
    const float span = wlHi - wlLo;
    const float b0 = wlLo - AWIN, b1 = wlLo - NWIN;
    const float b2 = wlHi + NWIN, b3 = wlHi + AWIN;
    const float n1w = fmaf(span, 1.0f / 3.0f, wlLo);
    const float n2w = fmaf(span, 2.0f / 3.0f, wlLo);

    if (tid < 4) sIdx[tid] = -1;
    __syncthreads();

    // ---- stream all lines once: boundaries + far sums + near/mid stash ----
    int c0 = -1, c1 = -1, c2 = -1, c3 = -1;
    float S0 = 0.f, S1 = 0.f, S2 = 0.f, S3 = 0.f;
    int    st_l = -1;
    float4 st_a;
    float  st_cg = 0.f;

    #pragma unroll 2
    for (int l = tid; l < L; l += BLOCK) {
        float4 a  = g_A[l];
        float  lc = a.x;

        if (lc < b0) c0 = l;
        if (lc < b1) c1 = l;
        if (lc < b2) c2 = l;
        if (lc < b3) c3 = l;

        if (lc >= b0 && lc < b3) {
            st_l = l; st_a = a; st_cg = g_B[l];
        } else {
            float d0 = wlLo - lc, d1 = n1w - lc, d2 = n2w - lc, d3 = wlHi - lc;
            float e0 = fmaf(d0, d0, a.y), e1 = fmaf(d1, d1, a.y);
            float e2 = fmaf(d2, d2, a.y), e3 = fmaf(d3, d3, a.y);
            float p01 = e0 * e1, p23 = e2 * e3;
            float r   = frcp(p01 * p23);
            float r01 = r * p23, r23 = r * p01;
            S0 = fmaf(a.z * e1, r01, S0);
            S1 = fmaf(a.z * e0, r01, S1);
            S2 = fmaf(a.z * e3, r23, S2);
            S3 = fmaf(a.z * e2, r23, S3);
        }
    }

    #pragma unroll
    for (int o = 16; o; o >>= 1) {
        S0 += __shfl_xor_sync(0xFFFFFFFFu, S0, o);
        S1 += __shfl_xor_sync(0xFFFFFFFFu, S1, o);
        S2 += __shfl_xor_sync(0xFFFFFFFFu, S2, o);
        S3 += __shfl_xor_sync(0xFFFFFFFFu, S3, o);
    }
    if (lane == 0) {
        sWredF[w]              = S0;
        sWredF[NWARPS + w]     = S1;
        sWredF[2 * NWARPS + w] = S2;
        sWredF[3 * NWARPS + w] = S3;
    }
    if (c0 >= 0) atomicMax(&sIdx[0], c0);
    if (c1 >= 0) atomicMax(&sIdx[1], c1);
    if (c2 >= 0) atomicMax(&sIdx[2], c2);
    if (c3 >= 0) atomicMax(&sIdx[3], c3);
    __syncthreads();

    const int alo = sIdx[0] + 1;
    const int nlo = sIdx[1] + 1;
    const int nhi = sIdx[2] + 1;
    const int ahi = sIdx[3] + 1;
    const int acnt  = min(ahi - alo, SMEM_CAP);
    const int nloc0 = min(nlo - alo, acnt);
    const int nloc1 = min(nhi - alo, acnt);

    if (st_l >= 0) {
        int li = st_l - alo;
        if (li >= 0 && li < SMEM_CAP) { sA[li] = st_a; sB[li] = st_cg; }
    }
    if (tid < 4) {
        float s = 0.f;
        #pragma unroll
        for (int k = 0; k < NWARPS; k++) s += sWredF[tid * NWARPS + k];
        sS[tid] = s;
    }
    __syncthreads();

    // ---- mid field: 16 uniform nodes, warp w -> node w ----
    if (w < 16) {
        float nodeM = fmaf((float)w, span * (1.0f / 15.0f), wlLo);
        float accM = 0.f;
        for (int j = lane; j < nloc0; j += 32) {
            float4 a = sA[j];
            float d = nodeM - a.x;
            accM = fmaf(a.z, frcp(fmaf(d, d, a.y)), accM);
        }
        for (int j = nloc1 + lane; j < acnt; j += 32) {
            float4 a = sA[j];
            float d = nodeM - a.x;
            accM = fmaf(a.z, frcp(fmaf(d, d, a.y)), accM);
        }
        #pragma unroll
        for (int o = 16; o; o >>= 1) accM += __shfl_xor_sync(0xFFFFFFFFu, accM, o);
        if (lane == 0) sMid[w] = accM;
    }

    // ---- near field: exact product, 1 pixel/thread ----
    const int   p   = p0 + tid;
    const float wlp = wl[min(p, npix - 1)];

    const float wLo3 = __shfl_sync(0xFFFFFFFFu, wlp, 0)  - GWIN;
    const float wHi3 = __shfl_sync(0xFFFFFFFFu, wlp, 31) + GWIN;
    int glo, ghi;
    {
        int a = nloc0, b = nloc1;
        while (a < b) { int m = (a + b) >> 1; if (sA[m].x < wLo3) a = m + 1; else b = m; }
        glo = a;
        a = glo; b = nloc1;
        while (a < b) { int m = (a + b) >> 1; if (sA[m].x <= wHi3) a = m + 1; else b = m; }
        ghi = a;
    }

    float prod = 1.0f;
    int j = nloc0;
    #pragma unroll 2
    for (; j + 1 < glo; j += 2) {
        float4 a0 = sA[j], a1 = sA[j + 1];
        float d0 = wlp - a0.x, d1 = wlp - a1.x;
        float e0 = fmaf(d0, d0, a0.y), e1 = fmaf(d1, d1, a1.y);
        float r  = frcp(e0 * e1);
        prod = fmaf(-(a0.z * e1) * r, prod, prod);
        prod = fmaf(-(a1.z * e0) * r, prod, prod);
    }
    if (j < glo) {
        float4 a = sA[j];
        float d = wlp - a.x;
        prod = fmaf(-(a.z * frcp(fmaf(d, d, a.y))), prod, prod);
    }
    for (j = glo; j < ghi; ++j) {
        float4 a  = sA[j];
        float  cg = sB[j];
        float d   = wlp - a.x;
        float d2  = d * d;
        float vl  = a.z * frcp(d2 + a.y);
        float v   = fmaf(cg, fex2(d2 * a.w), vl);
        prod = fmaf(-v, prod, prod);
    }
    j = ghi;
    #pragma unroll 2
    for (; j + 1 < nloc1; j += 2) {
        float4 a0 = sA[j], a1 = sA[j + 1];
        float d0 = wlp - a0.x, d1 = wlp - a1.x;
        float e0 = fmaf(d0, d0, a0.y), e1 = fmaf(d1, d1, a1.y);
        float r  = frcp(e0 * e1);
        prod = fmaf(-(a0.z * e1) * r, prod, prod);
        prod = fmaf(-(a1.z * e0) * r, prod, prod);
    }
    if (j < nloc1) {
        float4 a = sA[j];
        float d = wlp - a.x;
        prod = fmaf(-(a.z * frcp(fmaf(d, d, a.y))), prod, prod);
    }

    __syncthreads();   // sMid visible

    // ---- epilogue ----
    if (tid < cnt && p < npix) {
        const float ic = frcp((float)(cnt - 1));

        float s = (float)tid * (3.0f * ic);
        float sm1 = s - 1.0f, sm2 = s - 2.0f, sm3 = s - 3.0f;
        float Sfar = (sm1 * sm2 * sm3) * (-1.0f / 6.0f) * sS[0]
                   + (s   * sm2 * sm3) * ( 0.5f       ) * sS[1]
                   + (s   * sm1 * sm3) * (-0.5f       ) * sS[2]
                   + (s   * sm1 * sm2) * ( 1.0f / 6.0f) * sS[3];

        float t  = (float)tid * (15.0f * ic);
        int   i  = min(max((int)t, 1), 13);
        float x  = t - (float)i;
        float xp1 = x + 1.0f, xm1 = x - 1.0f, xm2 = x - 2.0f;
        float Smid = (-x   * xm1 * xm2 * (1.0f / 6.0f)) * sMid[i - 1]
                   + ( xp1 * xm1 * xm2 * 0.5f         ) * sMid[i]
                   + (-xp1 * x   * xm2 * 0.5f         ) * sMid[i + 1]
                   + ( xp1 * x   * xm1 * (1.0f / 6.0f)) * sMid[i + 2];

        float xw   = (wlp - 10500.0f) * (1.0f / 2500.0f);
        float polw = pa[0] + (pb[0] + pc[0] * xw) * xw;
        out[p] = prod * fex2(-(Sfar + Smid) * (float)LOG2E) * polw;
    }
}

extern "C" void kernel_launch(void* const* d_in, const int* in_sizes, int n_in,
                              void* d_out, int out_size) {
    const float* wl   = (const float*)d_in[0];
    const float* lam  = (const float*)d_in[1];
    const float* amps = (const float*)d_in[2];
    const float* sw   = (const float*)d_in[3];
    const float* gw   = (const float*)d_in[4];
    const float* pa   = (const float*)d_in[5];
    const float* pb   = (const float*)d_in[6];
    const float* pc   = (const float*)d_in[7];
    float* out = (float*)d_out;

    int npix = in_sizes[0];
    int L    = in_sizes[1];

    precomp_kernel<<<(L + 255) / 256, 256>>>(lam, amps, sw, gw, L);
    int nchunks = (npix + CHUNK - 1) / CHUNK;
    fused_kernel<<<nchunks, BLOCK>>>(wl, npix, L, pa, pb, pc, out);
}

// round 8
// speedup vs baseline: 1.1910x; 1.1910x over previous
#include <cuda_runtime.h>

// ---------------------------------------------------------------------------
// Single fused kernel. out[p] = prod_l (1 - V[l,p]) * poly(p), V pseudo-Voigt.
// CTA = 676-px chunk (grid = 148 = one wave), BLOCK = 704, 1 px/thread.
//
// 3-level hierarchy:
//  CTA-far  (> 20 A from chunk): linearized lorentz at 4 chunk nodes (cubic),
//           accumulated inline during the streaming/precomp pass, batched rcp.
//  CTA-mid  (4..20 A from chunk): linearized lorentz at 16 uniform nodes
//           (piecewise cubic), warp w -> node w.
//  chunk-near (<= 4 A from chunk), split per warp:
//    warp-near (<= 4 A of warp's 0.64 A pixel span): exact voigt per pixel
//    warp-mid  (rest): lorentz at 3 warp nodes, quadratic interp (err ~2e-6)
// Boundary indices via running max + atomicMax during the streaming pass;
// warp-near range via ballot scan (sorted lam -> contiguous).
// Error budget: linearization ~1e-6, CTA-mid ~1e-5, warp-mid ~2e-6.
// ---------------------------------------------------------------------------

#define BLOCK     704
#define NWARPS    22
#define CHUNK     676
#define NWIN      4.0f
#define AWIN      20.0f
#define WNWIN     4.0f
#define SMEM_CAP  192
#define LOG2E     1.4426950408889634f
#define FULLM     0xFFFFFFFFu

__device__ __forceinline__ float frcp(float x) {
    float r; asm("rcp.approx.ftz.f32 %0, %1;" : "=f"(r) : "f"(x)); return r;
}
__device__ __forceinline__ float fex2(float x) {
    float r; asm("ex2.approx.ftz.f32 %0, %1;" : "=f"(r) : "f"(x)); return r;
}
__device__ __forceinline__ float flg2(float x) {
    float r; asm("lg2.approx.ftz.f32 %0, %1;" : "=f"(r) : "f"(x)); return r;
}

__global__ void __launch_bounds__(BLOCK)
fused_kernel(const float* __restrict__ wl, int npix, int L,
             const float* __restrict__ lam,
             const float* __restrict__ amps,
             const float* __restrict__ sw,
             const float* __restrict__ gw,
             const float* __restrict__ pa,
             const float* __restrict__ pb,
             const float* __restrict__ pc,
             float* __restrict__ out) {
    __shared__ float4 sA[SMEM_CAP];          // {lam, g^2, c_lor, m}
    __shared__ float  sB[SMEM_CAP];          // c_gauss
    __shared__ float  sWredF[4 * NWARPS];
    __shared__ float  sS[4];
    __shared__ float  sMid[16];
    __shared__ int    sIdx[4];

    const int tid  = threadIdx.x;
    const int w    = tid >> 5, lane = tid & 31;
    const int p0   = blockIdx.x * CHUNK;
    const int cnt  = min(CHUNK, npix - p0);
    const int p    = p0 + tid;
    const float wlp = wl[min(p, npix - 1)];

    const float wlLo = wl[p0];
    const float wlHi = wl[p0 + cnt - 1];
    const float span = wlHi - wlLo;
    const float b0 = wlLo - AWIN, b1 = wlLo - NWIN;
    const float b2 = wlHi + NWIN, b3 = wlHi + AWIN;
    const float n1w = fmaf(span, 1.0f / 3.0f, wlLo);
    const float n2w = fmaf(span, 2.0f / 3.0f, wlLo);

    if (tid < 4) sIdx[tid] = -1;
    __syncthreads();

    // ---- stream all lines: constants + boundaries + far sums + stash ----
    int c0 = -1, c1 = -1, c2 = -1, c3 = -1;
    float S0 = 0.f, S1 = 0.f, S2 = 0.f, S3 = 0.f;
    int    st_l = -1;
    float4 st_a;
    float  st_cg = 0.f;

    #pragma unroll 2
    for (int l = tid; l < L; l += BLOCK) {
        float lc    = lam[l];
        float sigma = fex2(sw[l] * LOG2E);
        float gamma = fex2(gw[l] * LOG2E);
        float amp   = fex2(amps[l] * LOG2E);
        float fg = 2.3548f * sigma;
        float fl = 2.0f * gamma;
        float fg2 = fg * fg;
        float fl2 = fl * fl;
        float poly = fg2 * fg2 * fg
                   + 2.69269f * fg2 * fg2 * fl
                   + 2.42843f * fg2 * fg  * fl2
                   + 4.47163f * fg2 * fl  * fl2
                   + 0.07842f * fg  * fl2 * fl2
                   + fl2 * fl2 * fl;
        float fr  = fl * fex2(-0.2f * flg2(poly));
        float eta = fr * (1.36603f + fr * (-0.47719f + fr * 0.11116f));
        float g2  = gamma * gamma;
        float cl  = amp * eta * gamma * 0.3183098862f;

        if (lc < b0) c0 = l;
        if (lc < b1) c1 = l;
        if (lc < b2) c2 = l;
        if (lc < b3) c3 = l;

        if (lc >= b0 && lc < b3) {
            float invs = frcp(sigma);
            st_l = l;
            st_a = make_float4(lc, g2, cl, -0.72134752f * invs * invs);
            st_cg = amp * (1.0f - eta) * invs * 0.39894228f;
        } else {
            float d0 = wlLo - lc, d1 = n1w - lc, d2 = n2w - lc, d3 = wlHi - lc;
            float e0 = fmaf(d0, d0, g2), e1 = fmaf(d1, d1, g2);
            float e2 = fmaf(d2, d2, g2), e3 = fmaf(d3, d3, g2);
            float p01 = e0 * e1, p23 = e2 * e3;
            float r   = frcp(p01 * p23);
            float r01 = r * p23, r23 = r * p01;
            S0 = fmaf(cl * e1, r01, S0);
            S1 = fmaf(cl * e0, r01, S1);
            S2 = fmaf(cl * e3, r23, S2);
            S3 = fmaf(cl * e2, r23, S3);
        }
    }

    #pragma unroll
    for (int o = 16; o; o >>= 1) {
        S0 += __shfl_xor_sync(FULLM, S0, o);
        S1 += __shfl_xor_sync(FULLM, S1, o);
        S2 += __shfl_xor_sync(FULLM, S2, o);
        S3 += __shfl_xor_sync(FULLM, S3, o);
    }
    if (lane == 0) {
        sWredF[w]              = S0;
        sWredF[NWARPS + w]     = S1;
        sWredF[2 * NWARPS + w] = S2;
        sWredF[3 * NWARPS + w] = S3;
    }
    if (c0 >= 0) atomicMax(&sIdx[0], c0);
    if (c1 >= 0) atomicMax(&sIdx[1], c1);
    if (c2 >= 0) atomicMax(&sIdx[2], c2);
    if (c3 >= 0) atomicMax(&sIdx[3], c3);
    __syncthreads();

    const int alo = sIdx[0] + 1;
    const int nlo = sIdx[1] + 1;
    const int nhi = sIdx[2] + 1;
    const int ahi = sIdx[3] + 1;
    const int acnt  = min(ahi - alo, SMEM_CAP);
    const int nloc0 = min(nlo - alo, acnt);
    const int nloc1 = min(nhi - alo, acnt);

    if (st_l >= 0) {
        int li = st_l - alo;
        if (li >= 0 && li < SMEM_CAP) { sA[li] = st_a; sB[li] = st_cg; }
    }
    if (tid < 4) {
        float s = 0.f;
        #pragma unroll
        for (int k = 0; k < NWARPS; k++) s += sWredF[tid * NWARPS + k];
        sS[tid] = s;
    }
    __syncthreads();

    // ---- CTA-mid: 16 uniform nodes, warp w -> node w ----
    if (w < 16) {
        float nodeM = fmaf((float)w, span * (1.0f / 15.0f), wlLo);
        float accM = 0.f;
        for (int j = lane; j < nloc0; j += 32) {
            float4 a = sA[j];
            float d = nodeM - a.x;
            accM = fmaf(a.z, frcp(fmaf(d, d, a.y)), accM);
        }
        for (int j = nloc1 + lane; j < acnt; j += 32) {
            float4 a = sA[j];
            float d = nodeM - a.x;
            accM = fmaf(a.z, frcp(fmaf(d, d, a.y)), accM);
        }
        #pragma unroll
        for (int o = 16; o; o >>= 1) accM += __shfl_xor_sync(FULLM, accM, o);
        if (lane == 0) sMid[w] = accM;
    }

    // ---- warp-level classification of the chunk-near range ----
    const float x0n = __shfl_sync(FULLM, wlp, 0);
    const float x2n = __shfl_sync(FULLM, wlp, 31);
    const float wLo = x0n - WNWIN, wHi = x2n + WNWIN;
    int glo = nloc1, ghi = nloc0;
    for (int base = nloc0; base < nloc1; base += 32) {
        int idx = base + lane;
        bool in = (idx < nloc1) && (sA[idx].x >= wLo) && (sA[idx].x <= wHi);
        unsigned m = __ballot_sync(FULLM, in);
        if (m) {
            glo = min(glo, base + (__ffs(m) - 1));
            ghi = max(ghi, base + (31 - __clz(m)) + 1);
        }
    }
    if (ghi < glo) { glo = nloc0; ghi = nloc0; }

    // ---- warp-mid: lorentz at 3 warp nodes (batched rcp), lane-strided ----
    const float x1n = 0.5f * (x0n + x2n);
    float M0 = 0.f, M1 = 0.f, M2 = 0.f;
    for (int j = nloc0 + lane; j < nloc1; j += 32) {
        if (j >= glo && j < ghi) continue;          // exact-handled
        float4 a = sA[j];
        float d0 = x0n - a.x, d1 = x1n - a.x, d2 = x2n - a.x;
        float e0 = fmaf(d0, d0, a.y);
        float e1 = fmaf(d1, d1, a.y);
        float e2 = fmaf(d2, d2, a.y);
        float p01 = e0 * e1;
        float r   = frcp(p01 * e2);
        float r01 = r * e2;                          // 1/(e0*e1)
        M0 = fmaf(a.z * e1, r01, M0);
        M1 = fmaf(a.z * e0, r01, M1);
        M2 = fmaf(a.z, r * p01, M2);
    }
    #pragma unroll
    for (int o = 16; o; o >>= 1) {
        M0 += __shfl_xor_sync(FULLM, M0, o);
        M1 += __shfl_xor_sync(FULLM, M1, o);
        M2 += __shfl_xor_sync(FULLM, M2, o);
    }

    // ---- warp-near: exact voigt product, dual accumulators ----
    float prodA = 1.0f, prodB = 1.0f;
    int j = glo;
    for (; j + 1 < ghi; j += 2) {
        float4 a0 = sA[j];     float cg0 = sB[j];
        float4 a1 = sA[j + 1]; float cg1 = sB[j + 1];
        float dd0 = wlp - a0.x, dd1 = wlp - a1.x;
        float q0 = dd0 * dd0,   q1 = dd1 * dd1;
        float v0 = fmaf(cg0, fex2(q0 * a0.w), a0.z * frcp(q0 + a0.y));
        float v1 = fmaf(cg1, fex2(q1 * a1.w), a1.z * frcp(q1 + a1.y));
        prodA = fmaf(-v0, prodA, prodA);
        prodB = fmaf(-v1, prodB, prodB);
    }
    if (j < ghi) {
        float4 a = sA[j]; float cg = sB[j];
        float dd = wlp - a.x;
        float q  = dd * dd;
        float v  = fmaf(cg, fex2(q * a.w), a.z * frcp(q + a.y));
        prodA = fmaf(-v, prodA, prodA);
    }
    float prod = prodA * prodB;

    __syncthreads();   // sMid, sS visible

    // ---- epilogue ----
    if (tid < cnt && p < npix) {
        const float ic = frcp((float)(cnt - 1));

        // CTA-far: cubic Lagrange on nodes {0,1,2,3}, s in [0,3]
        float s = (float)tid * (3.0f * ic);
        float sm1 = s - 1.0f, sm2 = s - 2.0f, sm3 = s - 3.0f;
        float Sfar = (sm1 * sm2 * sm3) * (-1.0f / 6.0f) * sS[0]
                   + (s   * sm2 * sm3) * ( 0.5f       ) * sS[1]
                   + (s   * sm1 * sm3) * (-0.5f       ) * sS[2]
                   + (s   * sm1 * sm2) * ( 1.0f / 6.0f) * sS[3];

        // CTA-mid: piecewise cubic on 16 uniform nodes
        float t  = (float)tid * (15.0f * ic);
        int   i  = min(max((int)t, 1), 13);
        float x  = t - (float)i;
        float xp1 = x + 1.0f, xm1 = x - 1.0f, xm2 = x - 2.0f;
        float Smid = (-x   * xm1 * xm2 * (1.0f / 6.0f)) * sMid[i - 1]
                   + ( xp1 * xm1 * xm2 * 0.5f         ) * sMid[i]
                   + (-xp1 * x   * xm2 * 0.5f         ) * sMid[i + 1]
                   + ( xp1 * x   * xm1 * (1.0f / 6.0f)) * sMid[i + 2];

        // warp-mid: quadratic on nodes {x0n, x1n, x2n}, u in [0,2]
        float hw = 0.5f * (x2n - x0n);
        float u  = (wlp - x0n) * frcp(hw);
        float um1 = u - 1.0f, um2 = u - 2.0f;
        float Swm = (um1 * um2 * 0.5f) * M0
                  + (u * (2.0f - u)  ) * M1
                  + (u * um1 * 0.5f  ) * M2;

        float xw   = (wlp - 10500.0f) * (1.0f / 2500.0f);
        float polw = pa[0] + (pb[0] + pc[0] * xw) * xw;
        out[p] = prod * fex2(-(Sfar + Smid + Swm) * (float)LOG2E) * polw;
    }
}

extern "C" void kernel_launch(void* const* d_in, const int* in_sizes, int n_in,
                              void* d_out, int out_size) {
    const float* wl   = (const float*)d_in[0];
    const float* lam  = (const float*)d_in[1];
    const float* amps = (const float*)d_in[2];
    const float* sw   = (const float*)d_in[3];
    const float* gw   = (const float*)d_in[4];
    const float* pa   = (const float*)d_in[5];
    const float* pb   = (const float*)d_in[6];
    const float* pc   = (const float*)d_in[7];
    float* out = (float*)d_out;

    int npix = in_sizes[0];
    int L    = in_sizes[1];

    int nchunks = (npix + CHUNK - 1) / CHUNK;
    fused_kernel<<<nchunks, BLOCK>>>(wl, npix, L, lam, amps, sw, gw,
                                     pa, pb, pc, out);
}